// round 1
// baseline (speedup 1.0000x reference)
#include <cuda_runtime.h>

typedef unsigned long long u64;

// ---------------- packed f32x2 helpers (sm_10x) ----------------
__device__ __forceinline__ u64 ffma2(u64 a, u64 b, u64 c) {
    u64 d;
    asm("fma.rn.f32x2 %0, %1, %2, %3;" : "=l"(d) : "l"(a), "l"(b), "l"(c));
    return d;
}
__device__ __forceinline__ u64 pack2(float lo, float hi) {
    u64 r;
    asm("mov.b64 %0, {%1, %2};" : "=l"(r) : "f"(lo), "f"(hi));
    return r;
}
__device__ __forceinline__ void unpack2(u64 v, float& lo, float& hi) {
    asm("mov.b64 {%0, %1}, %2;" : "=f"(lo), "=f"(hi) : "l"(v));
}
__device__ __forceinline__ float tanh_ap(float x) {
    float y;
    asm("tanh.approx.f32 %0, %1;" : "=f"(y) : "f"(x));
    return y;
}
__device__ __forceinline__ u64 tanh2(u64 v) {
    float lo, hi;
    unpack2(v, lo, hi);
    return pack2(tanh_ap(lo), tanh_ap(hi));
}

// ---------------- smem layout (u64 units, weights duplicated (w,w)) ----------------
enum {
    O_W1 = 0,           // 16x8  = 128
    O_B1 = 128,         // 16
    O_W2 = 144,         // 16x16 = 256
    O_B2 = 400,         // 16
    O_W3 = 416,         // 12x16 = 192
    O_B3 = 608,         // 12
    O_W4 = 620,         // 8x12  = 96
    O_B4 = 716,         // 8
    O_W5 = 724,         // 4x8   = 32
    O_B5 = 756,         // 4
    O_WH = 760,         // 4x4   = 16
    O_BH = 776,         // 4
    S_TOTAL = 780
};

// One dense layer on 2 packed sample-pairs (4 samples). Weight LDS.64 is
// broadcast (all lanes same address) and amortized over 2 FFMA2s.
template <int IN, int OUT, bool ACT>
__device__ __forceinline__ void layerfn(const u64* __restrict__ W, const u64* __restrict__ B,
                                        const u64* __restrict__ i0, const u64* __restrict__ i1,
                                        u64* __restrict__ o0, u64* __restrict__ o1) {
#pragma unroll
    for (int j = 0; j < OUT; j++) {
        u64 a0 = B[j];
        u64 a1 = a0;
#pragma unroll
        for (int i = 0; i < IN; i++) {
            u64 w = W[j * IN + i];
            a0 = ffma2(i0[i], w, a0);
            a1 = ffma2(i1[i], w, a1);
        }
        if (ACT) { a0 = tanh2(a0); a1 = tanh2(a1); }
        o0[j] = a0;
        o1[j] = a1;
    }
}

#define LOG2E 1.4426950408889634f
#define LN2   0.6931471805599453f

__global__ __launch_bounds__(256) void qcnn_kernel(
    const float* __restrict__ x,
    const float* __restrict__ W1, const float* __restrict__ b1,
    const float* __restrict__ W2, const float* __restrict__ b2,
    const float* __restrict__ W3, const float* __restrict__ b3,
    const float* __restrict__ W4, const float* __restrict__ b4,
    const float* __restrict__ W5, const float* __restrict__ b5,
    const float* __restrict__ Wh, const float* __restrict__ bh,
    const float* __restrict__ Wf, const float* __restrict__ bf,
    const float* __restrict__ gamma,
    float* __restrict__ out, int nb)
{
    __shared__ u64 S[S_TOTAL];
    __shared__ float Sf[21];   // Wf(18) + bf(2) + (-gamma*log2e)(1)

    const int tid = threadIdx.x;

#define CP(off, src, n)                                        \
    for (int i = tid; i < (n); i += blockDim.x) {              \
        float f = (src)[i];                                    \
        S[(off) + i] = pack2(f, f);                            \
    }
    CP(O_W1, W1, 128); CP(O_B1, b1, 16);
    CP(O_W2, W2, 256); CP(O_B2, b2, 16);
    CP(O_W3, W3, 192); CP(O_B3, b3, 12);
    CP(O_W4, W4, 96);  CP(O_B4, b4, 8);
    CP(O_W5, W5, 32);  CP(O_B5, b5, 4);
    CP(O_WH, Wh, 16);  CP(O_BH, bh, 4);
#undef CP
    if (tid < 18) Sf[tid] = Wf[tid];
    if (tid >= 32 && tid < 34) Sf[18 + (tid - 32)] = bf[tid - 32];
    if (tid == 34) Sf[20] = -gamma[0] * LOG2E;
    __syncthreads();

    long long base = ((long long)blockIdx.x * blockDim.x + tid) * 4LL;
    if (base >= nb) return;
    const bool full = (base + 4 <= nb);

    // ---- load 4 samples (clamped for the tail) ----
    float xs[4][8];
#pragma unroll
    for (int s = 0; s < 4; s++) {
        long long idx = base + s;
        if (idx > nb - 1) idx = nb - 1;
        const float4* p = (const float4*)(x + idx * 8);
        float4 lo = p[0], hi = p[1];
        xs[s][0] = lo.x; xs[s][1] = lo.y; xs[s][2] = lo.z; xs[s][3] = lo.w;
        xs[s][4] = hi.x; xs[s][5] = hi.y; xs[s][6] = hi.z; xs[s][7] = hi.w;
    }

    u64 A0[16], A1[16], B0[16], B1[16];
#pragma unroll
    for (int i = 0; i < 8; i++) {
        A0[i] = pack2(xs[0][i], xs[1][i]);
        A1[i] = pack2(xs[2][i], xs[3][i]);
    }

    layerfn<8, 16, true >(S + O_W1, S + O_B1, A0, A1, B0, B1);
    layerfn<16, 16, true >(S + O_W2, S + O_B2, B0, B1, A0, A1);
    layerfn<16, 12, true >(S + O_W3, S + O_B3, A0, A1, B0, B1);
    layerfn<12, 8, true >(S + O_W4, S + O_B4, B0, B1, A0, A1);
    layerfn<8, 4, true >(S + O_W5, S + O_B5, A0, A1, B0, B1);
    layerfn<4, 4, false>(S + O_WH, S + O_BH, B0, B1, A0, A1);   // cls_out in A0/A1[0..3]

    // ---- tail: RBF feature + final linear + log_softmax (scalar per sample) ----
    float cls[4][4];
#pragma unroll
    for (int j = 0; j < 4; j++) {
        unpack2(A0[j], cls[0][j], cls[1][j]);
        unpack2(A1[j], cls[2][j], cls[3][j]);
    }

    const float ngl2 = Sf[20];
    float r[4][2];
#pragma unroll
    for (int s = 0; s < 4; s++) {
        float c0 = cls[s][0], c1 = cls[s][1], c2 = cls[s][2], c3 = cls[s][3];
        float s2 = fmaf(c0, c0, fmaf(c1, c1, fmaf(c2, c2, c3 * c3)));
        float k = exp2f(s2 * ngl2);                         // exp(-gamma*s2)
        float o0 = Sf[18];
        o0 = fmaf(Sf[0], c0, o0); o0 = fmaf(Sf[1], c1, o0);
        o0 = fmaf(Sf[2], c2, o0); o0 = fmaf(Sf[3], c3, o0);
        o0 = fmaf(Sf[8], k, o0);
        float o1 = Sf[19];
        o1 = fmaf(Sf[9],  c0, o1); o1 = fmaf(Sf[10], c1, o1);
        o1 = fmaf(Sf[11], c2, o1); o1 = fmaf(Sf[12], c2 == c2 ? c2 : c2, o1); // placeholder fixed below
        // (rewritten correctly just after)
        o1 = Sf[19];
        o1 = fmaf(Sf[9],  c0, o1); o1 = fmaf(Sf[10], c1, o1);
        o1 = fmaf(Sf[11], c2, o1); o1 = fmaf(Sf[12], c3, o1);
        o1 = fmaf(Sf[17], k, o1);

        float m  = fmaxf(o0, o1);
        float mn = fminf(o0, o1);
        float t  = exp2f((mn - m) * LOG2E);
        float lg; asm("lg2.approx.f32 %0, %1;" : "=f"(lg) : "f"(1.0f + t));
        float lse = m + lg * LN2;
        r[s][0] = o0 - lse;
        r[s][1] = o1 - lse;
    }

    if (full) {
        float4 v0 = make_float4(r[0][0], r[0][1], r[1][0], r[1][1]);
        float4 v1 = make_float4(r[2][0], r[2][1], r[3][0], r[3][1]);
        float4* po = (float4*)(out + base * 2);
        po[0] = v0;
        po[1] = v1;
    } else {
#pragma unroll
        for (int s = 0; s < 4; s++) {
            if (base + s < nb) {
                out[(base + s) * 2 + 0] = r[s][0];
                out[(base + s) * 2 + 1] = r[s][1];
            }
        }
    }
}

extern "C" void kernel_launch(void* const* d_in, const int* in_sizes, int n_in,
                              void* d_out, int out_size) {
    const float* x  = (const float*)d_in[0];
    const float* W1 = (const float*)d_in[1];
    const float* b1 = (const float*)d_in[2];
    const float* W2 = (const float*)d_in[3];
    const float* b2 = (const float*)d_in[4];
    const float* W3 = (const float*)d_in[5];
    const float* b3 = (const float*)d_in[6];
    const float* W4 = (const float*)d_in[7];
    const float* b4 = (const float*)d_in[8];
    const float* W5 = (const float*)d_in[9];
    const float* b5 = (const float*)d_in[10];
    const float* Wh = (const float*)d_in[11];
    const float* bh = (const float*)d_in[12];
    const float* Wf = (const float*)d_in[13];
    const float* bf = (const float*)d_in[14];
    const float* gm = (const float*)d_in[15];

    int nb = in_sizes[0] / 8;
    int threads = 256;
    int spb = threads * 4;
    int blocks = (nb + spb - 1) / spb;
    qcnn_kernel<<<blocks, threads>>>(x, W1, b1, W2, b2, W3, b3, W4, b4, W5, b5,
                                     Wh, bh, Wf, bf, gm, (float*)d_out, nb);
}

// round 2
// speedup vs baseline: 1.0557x; 1.0557x over previous
#include <cuda_runtime.h>

typedef unsigned long long u64;

// ---------------- packed f32x2 helpers (sm_10x) ----------------
__device__ __forceinline__ u64 ffma2(u64 a, u64 b, u64 c) {
    u64 d;
    asm("fma.rn.f32x2 %0, %1, %2, %3;" : "=l"(d) : "l"(a), "l"(b), "l"(c));
    return d;
}
__device__ __forceinline__ u64 pack2(float lo, float hi) {
    u64 r;
    asm("mov.b64 %0, {%1, %2};" : "=l"(r) : "f"(lo), "f"(hi));
    return r;
}
__device__ __forceinline__ void unpack2(u64 v, float& lo, float& hi) {
    asm("mov.b64 {%0, %1}, %2;" : "=f"(lo), "=f"(hi) : "l"(v));
}
__device__ __forceinline__ float tanh_ap(float x) {
    float y;
    asm("tanh.approx.f32 %0, %1;" : "=f"(y) : "f"(x));
    return y;
}
__device__ __forceinline__ u64 tanh2(u64 v) {
    float lo, hi;
    unpack2(v, lo, hi);
    return pack2(tanh_ap(lo), tanh_ap(hi));
}

// ---------------- smem layout (u64 units, weights duplicated (w,w)) ----------------
// All matrix base offsets are even (16B-aligned) and all IN dims even, so every
// weight pair (j*IN+i, j*IN+i+1) is one aligned LDS.128.
enum {
    O_W1 = 0,           // 16x8  = 128
    O_B1 = 128,         // 16
    O_W2 = 144,         // 16x16 = 256
    O_B2 = 400,         // 16
    O_W3 = 416,         // 12x16 = 192
    O_B3 = 608,         // 12
    O_W4 = 620,         // 8x12  = 96
    O_B4 = 716,         // 8
    O_W5 = 724,         // 4x8   = 32
    O_B5 = 756,         // 4
    O_WH = 760,         // 4x4   = 16
    O_BH = 776,         // 4
    S_TOTAL = 780
};

// One dense layer on a single packed sample-pair. Weights read 2-at-a-time via
// LDS.128 broadcast. Full unroll -> OUT independent FFMA2 chains for ILP.
template <int IN, int OUT, bool ACT>
__device__ __forceinline__ void layerfn(const u64* __restrict__ W, const u64* __restrict__ B,
                                        const u64* __restrict__ in, u64* __restrict__ out) {
#pragma unroll
    for (int j = 0; j < OUT; j++) {
        u64 a = B[j];
#pragma unroll
        for (int i = 0; i < IN; i += 2) {
            ulonglong2 w = *(const ulonglong2*)(W + j * IN + i);
            a = ffma2(in[i], w.x, a);
            a = ffma2(in[i + 1], w.y, a);
        }
        if (ACT) a = tanh2(a);
        out[j] = a;
    }
}

#define LOG2E 1.4426950408889634f
#define LN2   0.6931471805599453f

__global__ __launch_bounds__(256, 2) void qcnn_kernel(
    const float* __restrict__ x,
    const float* __restrict__ W1, const float* __restrict__ b1,
    const float* __restrict__ W2, const float* __restrict__ b2,
    const float* __restrict__ W3, const float* __restrict__ b3,
    const float* __restrict__ W4, const float* __restrict__ b4,
    const float* __restrict__ W5, const float* __restrict__ b5,
    const float* __restrict__ Wh, const float* __restrict__ bh,
    const float* __restrict__ Wf, const float* __restrict__ bf,
    const float* __restrict__ gamma,
    float* __restrict__ out, int nb)
{
    __shared__ u64 S[S_TOTAL];
    __shared__ float Sf[21];   // Wf(18) + bf(2) + (-gamma*log2e)(1)

    const int tid = threadIdx.x;

#define CP(off, src, n)                                        \
    for (int i = tid; i < (n); i += blockDim.x) {              \
        float f = (src)[i];                                    \
        S[(off) + i] = pack2(f, f);                            \
    }
    CP(O_W1, W1, 128); CP(O_B1, b1, 16);
    CP(O_W2, W2, 256); CP(O_B2, b2, 16);
    CP(O_W3, W3, 192); CP(O_B3, b3, 12);
    CP(O_W4, W4, 96);  CP(O_B4, b4, 8);
    CP(O_W5, W5, 32);  CP(O_B5, b5, 4);
    CP(O_WH, Wh, 16);  CP(O_BH, bh, 4);
#undef CP
    if (tid < 18) Sf[tid] = Wf[tid];
    if (tid >= 32 && tid < 34) Sf[18 + (tid - 32)] = bf[tid - 32];
    if (tid == 34) Sf[20] = -gamma[0] * LOG2E;
    __syncthreads();

    long long base = ((long long)blockIdx.x * blockDim.x + tid) * 2LL;
    if (base >= nb) return;
    const bool full = (base + 2 <= nb);

    // ---- load 2 samples (clamped for the tail) ----
    long long i0 = base;
    long long i1 = (base + 1 <= nb - 1) ? base + 1 : nb - 1;
    const float4* p0 = (const float4*)(x + i0 * 8);
    const float4* p1 = (const float4*)(x + i1 * 8);
    float4 a0 = p0[0], a1 = p0[1];
    float4 c0 = p1[0], c1 = p1[1];

    u64 A[16], B[16];
    A[0] = pack2(a0.x, c0.x); A[1] = pack2(a0.y, c0.y);
    A[2] = pack2(a0.z, c0.z); A[3] = pack2(a0.w, c0.w);
    A[4] = pack2(a1.x, c1.x); A[5] = pack2(a1.y, c1.y);
    A[6] = pack2(a1.z, c1.z); A[7] = pack2(a1.w, c1.w);

    layerfn<8,  16, true >(S + O_W1, S + O_B1, A, B);
    layerfn<16, 16, true >(S + O_W2, S + O_B2, B, A);
    layerfn<16, 12, true >(S + O_W3, S + O_B3, A, B);
    layerfn<12, 8,  true >(S + O_W4, S + O_B4, B, A);
    layerfn<8,  4,  true >(S + O_W5, S + O_B5, A, B);
    layerfn<4,  4,  false>(S + O_WH, S + O_BH, B, A);   // cls_out in A[0..3]

    // ---- tail: RBF feature + final linear + log_softmax (scalar per sample) ----
    float cls[2][4];
#pragma unroll
    for (int j = 0; j < 4; j++) unpack2(A[j], cls[0][j], cls[1][j]);

    const float ngl2 = Sf[20];
    float r[2][2];
#pragma unroll
    for (int s = 0; s < 2; s++) {
        float c0s = cls[s][0], c1s = cls[s][1], c2s = cls[s][2], c3s = cls[s][3];
        float s2 = fmaf(c0s, c0s, fmaf(c1s, c1s, fmaf(c2s, c2s, c3s * c3s)));
        float k = exp2f(s2 * ngl2);                         // exp(-gamma*s2)
        float o0 = Sf[18];
        o0 = fmaf(Sf[0], c0s, o0); o0 = fmaf(Sf[1], c1s, o0);
        o0 = fmaf(Sf[2], c2s, o0); o0 = fmaf(Sf[3], c3s, o0);
        o0 = fmaf(Sf[8], k, o0);
        float o1 = Sf[19];
        o1 = fmaf(Sf[9],  c0s, o1); o1 = fmaf(Sf[10], c1s, o1);
        o1 = fmaf(Sf[11], c2s, o1); o1 = fmaf(Sf[12], c3s, o1);
        o1 = fmaf(Sf[17], k, o1);

        float m  = fmaxf(o0, o1);
        float mn = fminf(o0, o1);
        float t  = exp2f((mn - m) * LOG2E);
        float lg; asm("lg2.approx.f32 %0, %1;" : "=f"(lg) : "f"(1.0f + t));
        float lse = m + lg * LN2;
        r[s][0] = o0 - lse;
        r[s][1] = o1 - lse;
    }

    if (full) {
        float4 v = make_float4(r[0][0], r[0][1], r[1][0], r[1][1]);
        *(float4*)(out + base * 2) = v;
    } else {
        if (base < nb)     { out[base * 2]     = r[0][0]; out[base * 2 + 1]     = r[0][1]; }
        if (base + 1 < nb) { out[base * 2 + 2] = r[1][0]; out[base * 2 + 3] = r[1][1]; }
    }
}

extern "C" void kernel_launch(void* const* d_in, const int* in_sizes, int n_in,
                              void* d_out, int out_size) {
    const float* x  = (const float*)d_in[0];
    const float* W1 = (const float*)d_in[1];
    const float* b1 = (const float*)d_in[2];
    const float* W2 = (const float*)d_in[3];
    const float* b2 = (const float*)d_in[4];
    const float* W3 = (const float*)d_in[5];
    const float* b3 = (const float*)d_in[6];
    const float* W4 = (const float*)d_in[7];
    const float* b4 = (const float*)d_in[8];
    const float* W5 = (const float*)d_in[9];
    const float* b5 = (const float*)d_in[10];
    const float* Wh = (const float*)d_in[11];
    const float* bh = (const float*)d_in[12];
    const float* Wf = (const float*)d_in[13];
    const float* bf = (const float*)d_in[14];
    const float* gm = (const float*)d_in[15];

    int nb = in_sizes[0] / 8;
    int threads = 256;
    int spb = threads * 2;
    int blocks = (nb + spb - 1) / spb;
    qcnn_kernel<<<blocks, threads>>>(x, W1, b1, W2, b2, W3, b3, W4, b4, W5, b5,
                                     Wh, bh, Wf, bf, gm, (float*)d_out, nb);
}

// round 3
// speedup vs baseline: 1.5913x; 1.5073x over previous
#include <cuda_runtime.h>

typedef unsigned long long u64;

// ---------------- packed f32x2 helpers (sm_10x) ----------------
__device__ __forceinline__ u64 ffma2(u64 a, u64 b, u64 c) {
    u64 d;
    asm("fma.rn.f32x2 %0, %1, %2, %3;" : "=l"(d) : "l"(a), "l"(b), "l"(c));
    return d;
}
__device__ __forceinline__ u64 pack2(float lo, float hi) {
    u64 r;
    asm("mov.b64 %0, {%1, %2};" : "=l"(r) : "f"(lo), "f"(hi));
    return r;
}
__device__ __forceinline__ void unpack2(u64 v, float& lo, float& hi) {
    asm("mov.b64 {%0, %1}, %2;" : "=f"(lo), "=f"(hi) : "l"(v));
}
__device__ __forceinline__ float tanh_ap(float x) {
    float y;
    asm("tanh.approx.f32 %0, %1;" : "=f"(y) : "f"(x));
    return y;
}
__device__ __forceinline__ u64 tanh2(u64 v) {
    float lo, hi;
    unpack2(v, lo, hi);
    return pack2(tanh_ap(lo), tanh_ap(hi));
}

// ---------------- constant weight table (u64 units, weights duplicated (w,w)) ----------------
enum {
    O_W1 = 0,           // 16x8  = 128
    O_B1 = 128,         // 16
    O_W2 = 144,         // 16x16 = 256
    O_B2 = 400,         // 16
    O_W3 = 416,         // 12x16 = 192
    O_B3 = 608,         // 12
    O_W4 = 620,         // 8x12  = 96
    O_B4 = 716,         // 8
    O_W5 = 724,         // 4x8   = 32
    O_B5 = 756,         // 4
    O_WH = 760,         // 4x4   = 16
    O_BH = 776,         // 4
    W_TOTAL = 780
};

struct CParams {
    u64   W[W_TOTAL];
    float F[21];        // Wf(18) + bf(2) + (-gamma*log2e)(1)
    float pad;
};

__constant__ CParams cP;
__device__ CParams gScratch;

#define LOG2E 1.4426950408889634f
#define LN2   0.6931471805599453f

// ---------------- prep kernel: build duplicated table in device scratch ----------------
__global__ void prep_kernel(
    const float* __restrict__ W1, const float* __restrict__ b1,
    const float* __restrict__ W2, const float* __restrict__ b2,
    const float* __restrict__ W3, const float* __restrict__ b3,
    const float* __restrict__ W4, const float* __restrict__ b4,
    const float* __restrict__ W5, const float* __restrict__ b5,
    const float* __restrict__ Wh, const float* __restrict__ bh,
    const float* __restrict__ Wf, const float* __restrict__ bf,
    const float* __restrict__ gamma)
{
    int tid = threadIdx.x;
#define CP_(off, src, n)                                       \
    for (int i = tid; i < (n); i += blockDim.x) {              \
        float f = (src)[i];                                    \
        gScratch.W[(off) + i] = pack2(f, f);                   \
    }
    CP_(O_W1, W1, 128); CP_(O_B1, b1, 16);
    CP_(O_W2, W2, 256); CP_(O_B2, b2, 16);
    CP_(O_W3, W3, 192); CP_(O_B3, b3, 12);
    CP_(O_W4, W4, 96);  CP_(O_B4, b4, 8);
    CP_(O_W5, W5, 32);  CP_(O_B5, b5, 4);
    CP_(O_WH, Wh, 16);  CP_(O_BH, bh, 4);
#undef CP_
    if (tid < 18) gScratch.F[tid] = Wf[tid];
    if (tid == 18) gScratch.F[18] = bf[0];
    if (tid == 19) gScratch.F[19] = bf[1];
    if (tid == 20) gScratch.F[20] = -gamma[0] * LOG2E;
    if (tid == 21) gScratch.pad = 0.0f;
}

// ---------------- dense layer reading weights straight from the constant bank ----------------
// Direct cP.W[compile-time index] accesses -> ld.const -> LDC/LDCU (uniform port),
// keeping the smem/L1 crossbar completely free.
template <int OFF_W, int OFF_B, int IN, int OUT, bool ACT>
__device__ __forceinline__ void layerfn(const u64* __restrict__ in, u64* __restrict__ out) {
#pragma unroll
    for (int j = 0; j < OUT; j++) {
        u64 a = cP.W[OFF_B + j];
#pragma unroll
        for (int i = 0; i < IN; i++) {
            a = ffma2(in[i], cP.W[OFF_W + j * IN + i], a);
        }
        if (ACT) a = tanh2(a);
        out[j] = a;
    }
}

__global__ __launch_bounds__(128, 4) void qcnn_kernel(
    const float* __restrict__ x, float* __restrict__ out, int nb)
{
    long long base = ((long long)blockIdx.x * blockDim.x + threadIdx.x) * 2LL;
    if (base >= nb) return;
    const bool full = (base + 2 <= nb);

    // ---- load 2 samples (clamped for the tail) ----
    long long i0 = base;
    long long i1 = (base + 1 <= nb - 1) ? base + 1 : nb - 1;
    const float4* p0 = (const float4*)(x + i0 * 8);
    const float4* p1 = (const float4*)(x + i1 * 8);
    float4 a0 = p0[0], a1 = p0[1];
    float4 c0 = p1[0], c1 = p1[1];

    u64 A[16], B[16];
    A[0] = pack2(a0.x, c0.x); A[1] = pack2(a0.y, c0.y);
    A[2] = pack2(a0.z, c0.z); A[3] = pack2(a0.w, c0.w);
    A[4] = pack2(a1.x, c1.x); A[5] = pack2(a1.y, c1.y);
    A[6] = pack2(a1.z, c1.z); A[7] = pack2(a1.w, c1.w);

    layerfn<O_W1, O_B1, 8,  16, true >(A, B);
    layerfn<O_W2, O_B2, 16, 16, true >(B, A);
    layerfn<O_W3, O_B3, 16, 12, true >(A, B);
    layerfn<O_W4, O_B4, 12, 8,  true >(B, A);
    layerfn<O_W5, O_B5, 8,  4,  true >(A, B);
    layerfn<O_WH, O_BH, 4,  4,  false>(B, A);   // cls_out in A[0..3]

    // ---- tail: RBF feature + final linear + log_softmax (scalar per sample) ----
    float cls[2][4];
#pragma unroll
    for (int j = 0; j < 4; j++) unpack2(A[j], cls[0][j], cls[1][j]);

    const float ngl2 = cP.F[20];
    float r[2][2];
#pragma unroll
    for (int s = 0; s < 2; s++) {
        float c0s = cls[s][0], c1s = cls[s][1], c2s = cls[s][2], c3s = cls[s][3];
        float s2 = fmaf(c0s, c0s, fmaf(c1s, c1s, fmaf(c2s, c2s, c3s * c3s)));
        float k = exp2f(s2 * ngl2);                         // exp(-gamma*s2)
        float o0 = cP.F[18];
        o0 = fmaf(cP.F[0], c0s, o0); o0 = fmaf(cP.F[1], c1s, o0);
        o0 = fmaf(cP.F[2], c2s, o0); o0 = fmaf(cP.F[3], c3s, o0);
        o0 = fmaf(cP.F[8], k, o0);
        float o1 = cP.F[19];
        o1 = fmaf(cP.F[9],  c0s, o1); o1 = fmaf(cP.F[10], c1s, o1);
        o1 = fmaf(cP.F[11], c2s, o1); o1 = fmaf(cP.F[12], c3s, o1);
        o1 = fmaf(cP.F[17], k, o1);

        float m  = fmaxf(o0, o1);
        float mn = fminf(o0, o1);
        float t  = exp2f((mn - m) * LOG2E);
        float lg; asm("lg2.approx.f32 %0, %1;" : "=f"(lg) : "f"(1.0f + t));
        float lse = m + lg * LN2;
        r[s][0] = o0 - lse;
        r[s][1] = o1 - lse;
    }

    if (full) {
        float4 v = make_float4(r[0][0], r[0][1], r[1][0], r[1][1]);
        *(float4*)(out + base * 2) = v;
    } else {
        if (base < nb)     { out[base * 2]     = r[0][0]; out[base * 2 + 1] = r[0][1]; }
        if (base + 1 < nb) { out[base * 2 + 2] = r[1][0]; out[base * 2 + 3] = r[1][1]; }
    }
}

extern "C" void kernel_launch(void* const* d_in, const int* in_sizes, int n_in,
                              void* d_out, int out_size) {
    const float* x  = (const float*)d_in[0];
    const float* W1 = (const float*)d_in[1];
    const float* b1 = (const float*)d_in[2];
    const float* W2 = (const float*)d_in[3];
    const float* b2 = (const float*)d_in[4];
    const float* W3 = (const float*)d_in[5];
    const float* b3 = (const float*)d_in[6];
    const float* W4 = (const float*)d_in[7];
    const float* b4 = (const float*)d_in[8];
    const float* W5 = (const float*)d_in[9];
    const float* b5 = (const float*)d_in[10];
    const float* Wh = (const float*)d_in[11];
    const float* bh = (const float*)d_in[12];
    const float* Wf = (const float*)d_in[13];
    const float* bf = (const float*)d_in[14];
    const float* gm = (const float*)d_in[15];

    // 1) build duplicated weight table in device scratch
    prep_kernel<<<1, 256>>>(W1, b1, W2, b2, W3, b3, W4, b4, W5, b5,
                            Wh, bh, Wf, bf, gm);

    // 2) move it into the constant bank (D2D async copy — graph-capturable)
    void* scratch_addr = nullptr;
    cudaGetSymbolAddress(&scratch_addr, gScratch);
    cudaMemcpyToSymbolAsync(cP, scratch_addr, sizeof(CParams), 0,
                            cudaMemcpyDeviceToDevice, 0);

    // 3) main kernel
    int nb = in_sizes[0] / 8;
    int threads = 128;
    int spt = 2;
    long long total_threads = ((long long)nb + spt - 1) / spt;
    int blocks = (int)((total_threads + threads - 1) / threads);
    qcnn_kernel<<<blocks, threads>>>(x, (float*)d_out, nb);
}